// round 17
// baseline (speedup 1.0000x reference)
#include <cuda_runtime.h>
#include <math.h>
#include <stdint.h>

#define B_ 16
#define L_ 2048
#define D_ 768
#define K_ 32
#define D4_ (D_ / 4)           // 192 float4 per row
#define CHUNK_ 32              // tokens per fused block
#define HALF_ (CHUNK_ / 2)     // 16
#define NCHUNK_ (L_ / CHUNK_)  // 64
#define ROWS_BYTES (CHUNK_ * D4_ * 16)   // 96 KB dynamic smem

// Persistent scratch (zero-initialized at load; scale_kernel re-zeroes the
// parts it consumes every call, so each kernel_launch sees clean state).
__device__ float g_H[B_ * K_ * D_];
__device__ float g_denom[B_ * K_];

__device__ __forceinline__ void cp_async16(uint32_t smem_addr, const void* gptr) {
    asm volatile("cp.async.cg.shared.global [%0], [%1], 16;"
                 :: "r"(smem_addr), "l"(gptr));
}
#define CP_COMMIT()  asm volatile("cp.async.commit_group;" ::: "memory")
#define CP_WAIT(n)   asm volatile("cp.async.wait_group %0;" :: "n"(n) : "memory")

// ---------------------------------------------------------------------------
// Fused kernel: token_hidden read from the memory system EXACTLY once, via
// cp.async double-buffered staging into 96 KB of dynamic smem.
// grid = (NCHUNK_, B_) = 1024 blocks, 192 threads.
//   copy half0 (rows 0-15), copy half1 (rows 16-31)   [async, 2 groups]
//   wait half0 -> phase1(dot/exp/denom) + phase2(accumulate) on half0
//   wait half1 -> phase1 + phase2 on half1
// All compute reads smem (conflict-free LDS.128).
// ---------------------------------------------------------------------------
__global__ __launch_bounds__(192)
void fused_kernel(const float* __restrict__ hid,
                  const float* __restrict__ amask,
                  const int* __restrict__ starts,
                  const int* __restrict__ ends,
                  const float* __restrict__ w,
                  const float* __restrict__ bias) {
    extern __shared__ float4 rows[];    // [CHUNK_][D4_] = 96 KB
    __shared__ float4 wsh[D4_];         // 3 KB
    __shared__ int   s_start[K_];
    __shared__ int   s_end[K_];
    __shared__ int   sid[CHUNK_];
    __shared__ float wgt[CHUNK_];

    const int c = blockIdx.x;           // chunk
    const int b = blockIdx.y;           // batch
    const int tid = threadIdx.x;
    const int wid = tid >> 5;           // 0..5
    const int lane = tid & 31;

    const int base = c * CHUNK_;
    const float4* hb = reinterpret_cast<const float4*>(
        hid + ((size_t)b * L_ + base) * D_);

    // Kick off the async copies FIRST so DRAM streaming starts immediately.
    const uint32_t rows_smem = (uint32_t)__cvta_generic_to_shared(rows);
    #pragma unroll
    for (int t = 0; t < HALF_; t++)
        cp_async16(rows_smem + (uint32_t)(t * D4_ + tid) * 16,
                   hb + (size_t)t * D4_ + tid);
    CP_COMMIT();
    #pragma unroll
    for (int t = HALF_; t < CHUNK_; t++)
        cp_async16(rows_smem + (uint32_t)(t * D4_ + tid) * 16,
                   hb + (size_t)t * D4_ + tid);
    CP_COMMIT();

    wsh[tid] = reinterpret_cast<const float4*>(w)[tid];
    if (tid < K_) {
        s_start[tid] = starts[b * K_ + tid];
        s_end[tid]   = ends[b * K_ + tid];
    }
    __syncthreads();

    // dependent scale_kernel can begin scheduling now
    asm volatile("griddepcontrol.launch_dependents;" ::: "memory");

    // ---- phase 0: span id per token ----
    if (tid < CHUNK_) {
        int l = base + tid;
        int lo = 0, hi = K_;
        while (lo < hi) {
            int mid = (lo + hi) >> 1;
            if (s_end[mid] > l) hi = mid; else lo = mid + 1;
        }
        sid[tid] = (lo < K_ && s_start[lo] <= l) ? lo : -1;
    }

    const float* am = amask + b * L_;
    const float bias0 = bias[0];

    #pragma unroll
    for (int h = 0; h < 2; h++) {
        const int h0 = h * HALF_;
        const int h1 = h0 + HALF_;

        if (h == 0) { CP_WAIT(1); } else { CP_WAIT(0); }
        __syncthreads();    // staged rows + (h==0: sid) visible to all

        // ---- phase 1: warp-per-token dot from SMEM -> wgt + denom ----
        for (int t = wid + h0; t < h1; t += 6) {
            int span = sid[t];
            if (span < 0) { if (lane == 0) wgt[t] = 0.0f; continue; }
            const float4* row = &rows[(size_t)t * D4_];
            float acc = 0.0f;
            #pragma unroll
            for (int i = 0; i < 6; i++) {
                float4 hv = row[lane + i * 32];
                float4 ww = wsh[lane + i * 32];
                acc += hv.x * ww.x + hv.y * ww.y + hv.z * ww.z + hv.w * ww.w;
            }
            #pragma unroll
            for (int off = 16; off > 0; off >>= 1)
                acc += __shfl_xor_sync(0xFFFFFFFFu, acc, off);
            if (lane == 0) {
                float e = (am[base + t] >= 0.5f) ? expf(acc + bias0) : 0.0f;
                wgt[t] = e;
                if (e > 0.0f) atomicAdd(&g_denom[b * K_ + span], e);
            }
        }
        __syncthreads();    // wgt ready

        // ---- phase 2: run-wise accumulation from SMEM ----
        int i = h0;
        while (i < h1) {
            int span = sid[i];
            int j = i + 1;
            while (j < h1 && sid[j] == span) j++;
            if (span >= 0) {
                float4 a0 = make_float4(0.f, 0.f, 0.f, 0.f);
                float4 a1 = make_float4(0.f, 0.f, 0.f, 0.f);
                float4 a2 = make_float4(0.f, 0.f, 0.f, 0.f);
                float4 a3 = make_float4(0.f, 0.f, 0.f, 0.f);
                int t = i;
                for (; t + 8 <= j; t += 8) {
                    float w0 = wgt[t],     w1 = wgt[t + 1], w2 = wgt[t + 2], w3 = wgt[t + 3];
                    float w4 = wgt[t + 4], w5 = wgt[t + 5], w6 = wgt[t + 6], w7 = wgt[t + 7];
                    float4 h0v = rows[(size_t)(t)     * D4_ + tid];
                    float4 h1v = rows[(size_t)(t + 1) * D4_ + tid];
                    float4 h2v = rows[(size_t)(t + 2) * D4_ + tid];
                    float4 h3v = rows[(size_t)(t + 3) * D4_ + tid];
                    float4 h4v = rows[(size_t)(t + 4) * D4_ + tid];
                    float4 h5v = rows[(size_t)(t + 5) * D4_ + tid];
                    float4 h6v = rows[(size_t)(t + 6) * D4_ + tid];
                    float4 h7v = rows[(size_t)(t + 7) * D4_ + tid];
                    a0.x += w0 * h0v.x; a0.y += w0 * h0v.y; a0.z += w0 * h0v.z; a0.w += w0 * h0v.w;
                    a1.x += w1 * h1v.x; a1.y += w1 * h1v.y; a1.z += w1 * h1v.z; a1.w += w1 * h1v.w;
                    a2.x += w2 * h2v.x; a2.y += w2 * h2v.y; a2.z += w2 * h2v.z; a2.w += w2 * h2v.w;
                    a3.x += w3 * h3v.x; a3.y += w3 * h3v.y; a3.z += w3 * h3v.z; a3.w += w3 * h3v.w;
                    a0.x += w4 * h4v.x; a0.y += w4 * h4v.y; a0.z += w4 * h4v.z; a0.w += w4 * h4v.w;
                    a1.x += w5 * h5v.x; a1.y += w5 * h5v.y; a1.z += w5 * h5v.z; a1.w += w5 * h5v.w;
                    a2.x += w6 * h6v.x; a2.y += w6 * h6v.y; a2.z += w6 * h6v.z; a2.w += w6 * h6v.w;
                    a3.x += w7 * h7v.x; a3.y += w7 * h7v.y; a3.z += w7 * h7v.z; a3.w += w7 * h7v.w;
                }
                for (; t + 4 <= j; t += 4) {
                    float w0 = wgt[t], w1 = wgt[t + 1], w2 = wgt[t + 2], w3 = wgt[t + 3];
                    float4 h0v = rows[(size_t)(t)     * D4_ + tid];
                    float4 h1v = rows[(size_t)(t + 1) * D4_ + tid];
                    float4 h2v = rows[(size_t)(t + 2) * D4_ + tid];
                    float4 h3v = rows[(size_t)(t + 3) * D4_ + tid];
                    a0.x += w0 * h0v.x; a0.y += w0 * h0v.y; a0.z += w0 * h0v.z; a0.w += w0 * h0v.w;
                    a1.x += w1 * h1v.x; a1.y += w1 * h1v.y; a1.z += w1 * h1v.z; a1.w += w1 * h1v.w;
                    a2.x += w2 * h2v.x; a2.y += w2 * h2v.y; a2.z += w2 * h2v.z; a2.w += w2 * h2v.w;
                    a3.x += w3 * h3v.x; a3.y += w3 * h3v.y; a3.z += w3 * h3v.z; a3.w += w3 * h3v.w;
                }
                for (; t < j; t++) {
                    float w0 = wgt[t];
                    float4 h0v = rows[(size_t)t * D4_ + tid];
                    a0.x += w0 * h0v.x; a0.y += w0 * h0v.y; a0.z += w0 * h0v.z; a0.w += w0 * h0v.w;
                }
                float rx = a0.x + a1.x + a2.x + a3.x;
                float ry = a0.y + a1.y + a2.y + a3.y;
                float rz = a0.z + a1.z + a2.z + a3.z;
                float rw = a0.w + a1.w + a2.w + a3.w;
                float* Hrow = g_H + ((size_t)(b * K_ + span)) * D_ + 4 * tid;
                atomicAdd(Hrow + 0, rx);
                atomicAdd(Hrow + 1, ry);
                atomicAdd(Hrow + 2, rz);
                atomicAdd(Hrow + 3, rw);
            }
            i = j;
        }
        if (h == 0) __syncthreads();   // protect wgt before half-1 phase 1
    }
}

// ---------------------------------------------------------------------------
// Kernel 2 (PDL dependent, R14-proven form): normalize g_H -> out, write
// sent_mask, re-zero consumed scratch. grid (K_, B_), 192 threads.
// ---------------------------------------------------------------------------
__global__ __launch_bounds__(192)
void scale_kernel(float* __restrict__ out) {
    asm volatile("griddepcontrol.wait;" ::: "memory");

    const int k = blockIdx.x;
    const int b = blockIdx.y;
    const int tid = threadIdx.x;
    const int bk = b * K_ + k;

    float d = g_denom[bk];
    float inv = (d > 0.0f) ? (1.0f / d) : 0.0f;

    float4* src4 = reinterpret_cast<float4*>(g_H + (size_t)bk * D_);
    float4* dst4 = reinterpret_cast<float4*>(out + (size_t)bk * D_);

    float4 v = src4[tid];
    v.x *= inv; v.y *= inv; v.z *= inv; v.w *= inv;
    dst4[tid] = v;
    src4[tid] = make_float4(0.0f, 0.0f, 0.0f, 0.0f);   // clean for next call

    if (tid == 0) {
        out[(size_t)B_ * K_ * D_ + bk] = (d > 0.0f) ? 1.0f : 0.0f;
        g_denom[bk] = 0.0f;                             // clean for next call
    }
}

// ---------------------------------------------------------------------------
extern "C" void kernel_launch(void* const* d_in, const int* in_sizes, int n_in,
                              void* d_out, int out_size) {
    const float* token_hidden   = (const float*)d_in[0];
    const float* attention_mask = (const float*)d_in[1];
    const int*   span_starts    = (const int*)d_in[2];
    const int*   span_ends      = (const int*)d_in[3];
    const float* w_pool         = (const float*)d_in[4];
    const float* b_pool         = (const float*)d_in[5];
    float* out = (float*)d_out;

    static int smem_set = 0;
    if (!smem_set) {
        cudaFuncSetAttribute(fused_kernel,
                             cudaFuncAttributeMaxDynamicSharedMemorySize,
                             ROWS_BYTES);
        smem_set = 1;
    }

    dim3 gridF(NCHUNK_, B_);
    fused_kernel<<<gridF, 192, ROWS_BYTES>>>(token_hidden, attention_mask,
                                             span_starts, span_ends,
                                             w_pool, b_pool);

    // scale_kernel attached via Programmatic Dependent Launch.
    cudaLaunchConfig_t cfg = {};
    cfg.gridDim  = dim3(K_, B_);
    cfg.blockDim = dim3(192);
    cfg.dynamicSmemBytes = 0;
    cfg.stream = 0;
    cudaLaunchAttribute attrs[1];
    attrs[0].id = cudaLaunchAttributeProgrammaticStreamSerialization;
    attrs[0].val.programmaticStreamSerializationAllowed = 1;
    cfg.attrs = attrs;
    cfg.numAttrs = 1;
    cudaLaunchKernelEx(&cfg, scale_kernel, out);
}